// round 7
// baseline (speedup 1.0000x reference)
#include <cuda_runtime.h>

// MaxPool3d k=2 s=2 fp32 [2,32,128,128,128] -> [2,32,64,64,64]
// v7 = v4 (best: block=512, exact grid, 4 outputs/thread, 8x float4 streaming
// loads) + write-through store (__stwt) to keep the output stream from
// contending with the read stream in L2.

#define W_IN    128
#define HW_IN   (128 * 128)
#define DHW_IN  (128 * 128 * 128)
#define W_OUT   64
#define HW_OUT  (64 * 64)
#define DHW_OUT (64 * 64 * 64)

__global__ void __launch_bounds__(512) maxpool3d_k2s2_v7(
    const float* __restrict__ in, float* __restrict__ out)
{
    int tid = blockIdx.x * blockDim.x + threadIdx.x;   // exact grid: no bounds check

    // tid -> (bc, d, h, q), q in [0,16): outputs w = 4q..4q+3
    int q  = tid & 15;
    int t1 = tid >> 4;
    int h  = t1 & 63;
    int t2 = t1 >> 6;
    int d  = t2 & 63;
    int bc = t2 >> 6;            // 0..63

    const float4* base = reinterpret_cast<const float4*>(
        in + (size_t)bc * DHW_IN + (size_t)(2 * d) * HW_IN + (size_t)(2 * h) * W_IN)
        + 2 * q;

    float4 r0a = __ldcs(base);
    float4 r0b = __ldcs(base + 1);
    float4 r1a = __ldcs(base + (W_IN / 4));
    float4 r1b = __ldcs(base + (W_IN / 4) + 1);
    float4 r2a = __ldcs(base + (HW_IN / 4));
    float4 r2b = __ldcs(base + (HW_IN / 4) + 1);
    float4 r3a = __ldcs(base + (HW_IN / 4 + W_IN / 4));
    float4 r3b = __ldcs(base + (HW_IN / 4 + W_IN / 4) + 1);

    float4 res;
    res.x = fmaxf(fmaxf(fmaxf(r0a.x, r0a.y), fmaxf(r1a.x, r1a.y)),
                  fmaxf(fmaxf(r2a.x, r2a.y), fmaxf(r3a.x, r3a.y)));
    res.y = fmaxf(fmaxf(fmaxf(r0a.z, r0a.w), fmaxf(r1a.z, r1a.w)),
                  fmaxf(fmaxf(r2a.z, r2a.w), fmaxf(r3a.z, r3a.w)));
    res.z = fmaxf(fmaxf(fmaxf(r0b.x, r0b.y), fmaxf(r1b.x, r1b.y)),
                  fmaxf(fmaxf(r2b.x, r2b.y), fmaxf(r3b.x, r3b.y)));
    res.w = fmaxf(fmaxf(fmaxf(r0b.z, r0b.w), fmaxf(r1b.z, r1b.w)),
                  fmaxf(fmaxf(r2b.z, r2b.w), fmaxf(r3b.z, r3b.w)));

    float4* op = reinterpret_cast<float4*>(
        out + (size_t)bc * DHW_OUT + (size_t)d * HW_OUT + (size_t)h * W_OUT) + q;
    __stwt(op, res);
}

extern "C" void kernel_launch(void* const* d_in, const int* in_sizes, int n_in,
                              void* d_out, int out_size)
{
    const float* in = (const float*)d_in[0];
    float* out = (float*)d_out;
    int n_quads = out_size / 4;              // 4,194,304 (divides 512 exactly)
    maxpool3d_k2s2_v7<<<n_quads / 512, 512>>>(in, out);
}

// round 8
// speedup vs baseline: 1.3380x; 1.3380x over previous
#include <cuda_runtime.h>

// MaxPool3d k=2 s=2 fp32 [2,32,128,128,128] -> [2,32,64,64,64]
// FINAL (== R4 best, 88.1us wall / 83.4us kernel / 6997 GB/s, 88.3% HBM spec):
// block=512, exact grid (no tail guard), 4 outputs/thread along W,
// 8x float4 streaming loads (__ldcs), 1x float4 streaming store (__stcs).
// Measured flat-or-negative alternatives: more ILP, persistent grid-stride,
// block=256, write-through stores. This is the HBM streaming ceiling.

#define W_IN    128
#define HW_IN   (128 * 128)
#define DHW_IN  (128 * 128 * 128)
#define W_OUT   64
#define HW_OUT  (64 * 64)
#define DHW_OUT (64 * 64 * 64)

__global__ void __launch_bounds__(512) maxpool3d_k2s2_final(
    const float* __restrict__ in, float* __restrict__ out)
{
    int tid = blockIdx.x * blockDim.x + threadIdx.x;   // exact grid: no bounds check

    // tid -> (bc, d, h, q), q in [0,16): outputs w = 4q..4q+3
    int q  = tid & 15;
    int t1 = tid >> 4;
    int h  = t1 & 63;
    int t2 = t1 >> 6;
    int d  = t2 & 63;
    int bc = t2 >> 6;            // 0..63

    const float4* base = reinterpret_cast<const float4*>(
        in + (size_t)bc * DHW_IN + (size_t)(2 * d) * HW_IN + (size_t)(2 * h) * W_IN)
        + 2 * q;

    float4 r0a = __ldcs(base);
    float4 r0b = __ldcs(base + 1);
    float4 r1a = __ldcs(base + (W_IN / 4));
    float4 r1b = __ldcs(base + (W_IN / 4) + 1);
    float4 r2a = __ldcs(base + (HW_IN / 4));
    float4 r2b = __ldcs(base + (HW_IN / 4) + 1);
    float4 r3a = __ldcs(base + (HW_IN / 4 + W_IN / 4));
    float4 r3b = __ldcs(base + (HW_IN / 4 + W_IN / 4) + 1);

    float4 res;
    res.x = fmaxf(fmaxf(fmaxf(r0a.x, r0a.y), fmaxf(r1a.x, r1a.y)),
                  fmaxf(fmaxf(r2a.x, r2a.y), fmaxf(r3a.x, r3a.y)));
    res.y = fmaxf(fmaxf(fmaxf(r0a.z, r0a.w), fmaxf(r1a.z, r1a.w)),
                  fmaxf(fmaxf(r2a.z, r2a.w), fmaxf(r3a.z, r3a.w)));
    res.z = fmaxf(fmaxf(fmaxf(r0b.x, r0b.y), fmaxf(r1b.x, r1b.y)),
                  fmaxf(fmaxf(r2b.x, r2b.y), fmaxf(r3b.x, r3b.y)));
    res.w = fmaxf(fmaxf(fmaxf(r0b.z, r0b.w), fmaxf(r1b.z, r1b.w)),
                  fmaxf(fmaxf(r2b.z, r2b.w), fmaxf(r3b.z, r3b.w)));

    float4* op = reinterpret_cast<float4*>(
        out + (size_t)bc * DHW_OUT + (size_t)d * HW_OUT + (size_t)h * W_OUT) + q;
    __stcs(op, res);
}

extern "C" void kernel_launch(void* const* d_in, const int* in_sizes, int n_in,
                              void* d_out, int out_size)
{
    const float* in = (const float*)d_in[0];
    float* out = (float*)d_out;
    int n_quads = out_size / 4;              // 4,194,304 (divides 512 exactly)
    maxpool3d_k2s2_final<<<n_quads / 512, 512>>>(in, out);
}

// round 11
// speedup vs baseline: 1.3463x; 1.0062x over previous
#include <cuda_runtime.h>

// MaxPool3d k=2 s=2 fp32 [2,32,128,128,128] -> [2,32,64,64,64]
// v9 (resubmit; R10 was an infra failure, kernel never ran).
// v4 best shape (block=512, exact grid, 4 outputs/thread) with the 8x
// 128-bit streaming loads fused into 4x 256-bit loads (ld.global.cs.v8.f32,
// Blackwell sm_100+). Each thread's two w-chunks per row are 32 contiguous,
// 32B-aligned bytes -> one LDG.E.256. Halves L1tex wavefront-queue entries.

#define W_IN    128
#define HW_IN   (128 * 128)
#define DHW_IN  (128 * 128 * 128)
#define W_OUT   64
#define HW_OUT  (64 * 64)
#define DHW_OUT (64 * 64 * 64)

__device__ __forceinline__ void ldg256_cs(const float* p, float4& a, float4& b)
{
    asm("ld.global.cs.v8.f32 {%0,%1,%2,%3,%4,%5,%6,%7}, [%8];"
        : "=f"(a.x), "=f"(a.y), "=f"(a.z), "=f"(a.w),
          "=f"(b.x), "=f"(b.y), "=f"(b.z), "=f"(b.w)
        : "l"(p));
}

__global__ void __launch_bounds__(512) maxpool3d_k2s2_v9(
    const float* __restrict__ in, float* __restrict__ out)
{
    int tid = blockIdx.x * blockDim.x + threadIdx.x;   // exact grid: no bounds check

    // tid -> (bc, d, h, q), q in [0,16): outputs w = 4q..4q+3
    int q  = tid & 15;
    int t1 = tid >> 4;
    int h  = t1 & 63;
    int t2 = t1 >> 6;
    int d  = t2 & 63;
    int bc = t2 >> 6;            // 0..63

    const float* base = in + (size_t)bc * DHW_IN + (size_t)(2 * d) * HW_IN
                           + (size_t)(2 * h) * W_IN + 8 * q;   // 32B-aligned

    float4 r0a, r0b, r1a, r1b, r2a, r2b, r3a, r3b;
    ldg256_cs(base,                 r0a, r0b);   // (2d,   2h  )
    ldg256_cs(base + W_IN,          r1a, r1b);   // (2d,   2h+1)
    ldg256_cs(base + HW_IN,         r2a, r2b);   // (2d+1, 2h  )
    ldg256_cs(base + HW_IN + W_IN,  r3a, r3b);   // (2d+1, 2h+1)

    float4 res;
    res.x = fmaxf(fmaxf(fmaxf(r0a.x, r0a.y), fmaxf(r1a.x, r1a.y)),
                  fmaxf(fmaxf(r2a.x, r2a.y), fmaxf(r3a.x, r3a.y)));
    res.y = fmaxf(fmaxf(fmaxf(r0a.z, r0a.w), fmaxf(r1a.z, r1a.w)),
                  fmaxf(fmaxf(r2a.z, r2a.w), fmaxf(r3a.z, r3a.w)));
    res.z = fmaxf(fmaxf(fmaxf(r0b.x, r0b.y), fmaxf(r1b.x, r1b.y)),
                  fmaxf(fmaxf(r2b.x, r2b.y), fmaxf(r3b.x, r3b.y)));
    res.w = fmaxf(fmaxf(fmaxf(r0b.z, r0b.w), fmaxf(r1b.z, r1b.w)),
                  fmaxf(fmaxf(r2b.z, r2b.w), fmaxf(r3b.z, r3b.w)));

    float4* op = reinterpret_cast<float4*>(
        out + (size_t)bc * DHW_OUT + (size_t)d * HW_OUT + (size_t)h * W_OUT) + q;
    __stcs(op, res);
}

extern "C" void kernel_launch(void* const* d_in, const int* in_sizes, int n_in,
                              void* d_out, int out_size)
{
    const float* in = (const float*)d_in[0];
    float* out = (float*)d_out;
    int n_quads = out_size / 4;              // 4,194,304 (divides 512 exactly)
    maxpool3d_k2s2_v9<<<n_quads / 512, 512>>>(in, out);
}